// round 1
// baseline (speedup 1.0000x reference)
#include <cuda_runtime.h>
#include <stdint.h>

// Problem constants (fixed by the reference problem definition)
#define FEAT_DIM 128
#define BATCH    4
#define NY       512
#define NX       512
#define NPIX     (BATCH * NY * NX)   // 1,048,576

#define XT 64          // x-tile per block
#define PAD 129        // odd pad -> conflict-free transposed LDS

// 4 MB scratch: winning (max) voxel index per output pixel, -1 if empty.
__device__ int g_map[NPIX];

// ---------------------------------------------------------------------------
// Kernel 1: init map to -1 (vectorized)
// ---------------------------------------------------------------------------
__global__ void k_init_map() {
    int i = blockIdx.x * blockDim.x + threadIdx.x;   // int4 index
    int4 m1 = make_int4(-1, -1, -1, -1);
    if (i < NPIX / 4) {
        reinterpret_cast<int4*>(g_map)[i] = m1;
    }
}

// ---------------------------------------------------------------------------
// Kernel 2: last-write-wins == max voxel index wins -> atomicMax
// coors: [N,4] int32 (b, z, y, x)
// ---------------------------------------------------------------------------
__global__ void k_argmax_map(const int* __restrict__ coors, int n) {
    int i = blockIdx.x * blockDim.x + threadIdx.x;
    if (i >= n) return;
    int4 c = reinterpret_cast<const int4*>(coors)[i];  // b, z, y, x
    int flat = c.x * (NY * NX) + c.z * NX + c.w;
    atomicMax(&g_map[flat], i);
}

// ---------------------------------------------------------------------------
// Kernel 3: gather + transpose. One block per (b, y, x-tile of 64).
// Writes the FULL output (zeros for empty pixels) in coalesced order.
// ---------------------------------------------------------------------------
__global__ __launch_bounds__(256, 4)
void k_gather(const float* __restrict__ feat, float* __restrict__ out) {
    __shared__ float tile[XT * PAD];   // [x][c], padded
    __shared__ int   vidx[XT];

    int blk = blockIdx.x;              // 0 .. BATCH*NY*(NX/XT)-1
    int xt  = blk & (NX / XT - 1);     // 0..7
    int y   = (blk >> 3) & (NY - 1);   // 0..511
    int b   = blk >> 12;               // 0..3
    int x0  = xt * XT;

    int t = threadIdx.x;
    if (t < XT) vidx[t] = g_map[b * (NY * NX) + y * NX + x0 + t];
    __syncthreads();

    int warp = t >> 5, lane = t & 31;

    // Fill stage: one warp per x; coalesced 128B gmem reads of the feat row,
    // conflict-free smem stores (addr = xl*PAD + it*32 + lane).
    for (int xl = warp; xl < XT; xl += 8) {
        int v = vidx[xl];
        if (v >= 0) {
            const float* row = feat + (size_t)v * FEAT_DIM;
            #pragma unroll
            for (int it = 0; it < 4; it++)
                tile[xl * PAD + it * 32 + lane] = row[it * 32 + lane];
        } else {
            #pragma unroll
            for (int it = 0; it < 4; it++)
                tile[xl * PAD + it * 32 + lane] = 0.0f;
        }
    }
    __syncthreads();

    // Drain stage: 128 channels x 64 x's. Each warp-row writes 32 contiguous
    // x's for one channel: 128B coalesced STG; LDS addr = (xh+lane)*PAD + c
    // with PAD odd -> conflict-free.
    size_t obase = (((size_t)b * FEAT_DIM) * NY + y) * NX + x0;
    #pragma unroll 4
    for (int r = warp; r < FEAT_DIM * 2; r += 8) {
        int c  = r >> 1;
        int xh = (r & 1) << 5;
        out[obase + (size_t)c * (NY * NX) + xh + lane] = tile[(xh + lane) * PAD + c];
    }
}

// ---------------------------------------------------------------------------
extern "C" void kernel_launch(void* const* d_in, const int* in_sizes, int n_in,
                              void* d_out, int out_size) {
    const float* feat  = (const float*)d_in[0];
    const int*   coors = (const int*)d_in[1];
    float*       out   = (float*)d_out;

    int n = in_sizes[0] / FEAT_DIM;   // number of voxels

    // 1) map = -1
    k_init_map<<<(NPIX / 4 + 255) / 256, 256>>>();
    // 2) winner per pixel
    k_argmax_map<<<(n + 255) / 256, 256>>>(coors, n);
    // 3) gather + transpose full output
    k_gather<<<BATCH * NY * (NX / XT), 256>>>(feat, out);
}